// round 8
// baseline (speedup 1.0000x reference)
#include <cuda_runtime.h>
#include <cuda_fp16.h>
#include <cstdint>

#define M_TOK 64
#define N_OUT 8192
#define K_IN  8192
#define NG    64              // K groups per row (8192/128)
#define BN    32              // N columns per CTA
#define NTILES (N_OUT / BN)   // 256
#define WTOTAL (NTILES * NG)  // 16384 work units
#define NCTA  592             // 4 per SM on 148 SMs, all resident
#define BK    128
#define LDK   136
#define NTHREADS 128
#define ABYTES (M_TOK * LDK * 2)              // 17408
#define BBYTES (BN * LDK * 2)                 // 8704
#define SMEM_BYTES (2 * ABYTES + 2 * BBYTES)  // 52224 B -> 4 CTA/SM

__device__ __half   g_xh[M_TOK * K_IN];       // x in fp16 (1 MB)
__device__ uint32_t g_szp[NG * N_OUT];        // packed (s,z) half2 (2 MB)
__device__ float    g_part[NCTA * 2 * (64 * BN)];  // stream-K partials (~9.7 MB)

__device__ __forceinline__ int gsplit(int c) { return (int)(((long long)c * WTOTAL) / NCTA); }

// ---- prep: convert x to fp16 + pack (s,z) to half2 ----
__global__ void prep_kernel(const float* __restrict__ x, const float* __restrict__ sz) {
    const int NX = M_TOK * K_IN / 8;
    int t = blockIdx.x * blockDim.x + threadIdx.x;
    if (t < NX) {
        float4 v0 = *reinterpret_cast<const float4*>(x + (size_t)t * 8);
        float4 v1 = *reinterpret_cast<const float4*>(x + (size_t)t * 8 + 4);
        __half2 h0 = __floats2half2_rn(v0.x, v0.y);
        __half2 h1 = __floats2half2_rn(v0.z, v0.w);
        __half2 h2 = __floats2half2_rn(v1.x, v1.y);
        __half2 h3 = __floats2half2_rn(v1.z, v1.w);
        uint4 pk;
        pk.x = *reinterpret_cast<uint32_t*>(&h0);
        pk.y = *reinterpret_cast<uint32_t*>(&h1);
        pk.z = *reinterpret_cast<uint32_t*>(&h2);
        pk.w = *reinterpret_cast<uint32_t*>(&h3);
        *reinterpret_cast<uint4*>(g_xh + (size_t)t * 8) = pk;
    } else {
        int u = t - NX;
        float4 v0 = *reinterpret_cast<const float4*>(sz + (size_t)u * 8);
        float4 v1 = *reinterpret_cast<const float4*>(sz + (size_t)u * 8 + 4);
        __half2 a = __floats2half2_rn(v0.x, v0.y);
        __half2 b = __floats2half2_rn(v0.z, v0.w);
        __half2 c2 = __floats2half2_rn(v1.x, v1.y);
        __half2 d = __floats2half2_rn(v1.z, v1.w);
        uint4 pk;
        pk.x = *reinterpret_cast<uint32_t*>(&a);
        pk.y = *reinterpret_cast<uint32_t*>(&b);
        pk.z = *reinterpret_cast<uint32_t*>(&c2);
        pk.w = *reinterpret_cast<uint32_t*>(&d);
        *reinterpret_cast<uint4*>(g_szp + (size_t)u * 4) = pk;
    }
}

// ---- stream-K reduce: fixed contributor set per 32-wide ntile ----
__global__ void reduce_kernel(float* __restrict__ out) {
    int i2 = (blockIdx.x * blockDim.x + threadIdx.x) * 2;
    int m  = i2 >> 13;
    int n  = i2 & (N_OUT - 1);
    int nt = n >> 5, nl = n & 31;
    int X  = nt << 6;                      // first work unit of this ntile
    int c  = (int)(((long long)X * NCTA) / WTOTAL);
    while (gsplit(c + 1) <= X) ++c;
    float sx = 0.f, sy = 0.f;
    while (c < NCTA && gsplit(c) < X + 64) {
        int seg = ((gsplit(c) >> 6) == nt) ? 0 : 1;
        const float2 v = *reinterpret_cast<const float2*>(
            g_part + ((size_t)c * 2 + seg) * (64 * BN) + m * BN + nl);
        sx += v.x; sy += v.y;
        ++c;
    }
    *reinterpret_cast<float2*>(out + i2) = make_float2(sx, sy);
}

__device__ __forceinline__ void cp16(uint32_t dst, const void* src) {
    asm volatile("cp.async.cg.shared.global [%0], [%1], 16;" :: "r"(dst), "l"(src));
}
__device__ __forceinline__ void ldsm4(uint32_t& r0, uint32_t& r1, uint32_t& r2, uint32_t& r3,
                                      uint32_t a) {
    asm volatile("ldmatrix.sync.aligned.m8n8.x4.shared.b16 {%0,%1,%2,%3}, [%4];"
                 : "=r"(r0), "=r"(r1), "=r"(r2), "=r"(r3) : "r"(a));
}
__device__ __forceinline__ void mma_16816(float c[4],
                                          uint32_t a0, uint32_t a1, uint32_t a2, uint32_t a3,
                                          uint32_t b0, uint32_t b1) {
    asm volatile("mma.sync.aligned.m16n8k16.row.col.f32.f16.f16.f32 "
                 "{%0,%1,%2,%3}, {%4,%5,%6,%7}, {%8,%9}, {%0,%1,%2,%3};"
                 : "+f"(c[0]), "+f"(c[1]), "+f"(c[2]), "+f"(c[3])
                 : "r"(a0), "r"(a1), "r"(a2), "r"(a3), "r"(b0), "r"(b1));
}

__global__ void __launch_bounds__(NTHREADS, 4)
woq_gemm_kernel(const int* __restrict__ qw)
{
    extern __shared__ __half smem[];
    __half* Bs = smem + 2 * M_TOK * LDK;

    const int tid  = threadIdx.x;
    const int lane = tid & 31;
    const int warp = tid >> 5;   // 0..3 = m-tile
    const int cta  = blockIdx.x;

    const int w0 = gsplit(cta);
    const int w1 = gsplit(cta + 1);

    float acc[4][4];
    #pragma unroll
    for (int i = 0; i < 4; ++i)
        #pragma unroll
        for (int j = 0; j < 4; ++j) acc[i][j] = 0.f;

    const uint32_t s_base = (uint32_t)__cvta_generic_to_shared(smem);
    const uint32_t as_b = s_base;
    const uint32_t bs_b = s_base + 2 * ABYTES;

    const uint32_t a_off  = as_b + 2u * ((warp * 16 + (lane & 15)) * LDK + (lane >> 4) * 8);
    const uint32_t b_off0 = bs_b + 2u * (((lane & 7) + ((lane >> 4) << 3)) * LDK
                                         + ((lane >> 3) & 1) * 8);
    const uint32_t b_off1 = b_off0 + 2u * 16 * LDK;

    // x tile cp.async: 1024 16B units, 8 per thread (row tid/2, units (tid&1)*8..+7)
    const int xrow = tid >> 1;
    const int xu0  = (tid & 1) * 8;
    const __half* xsrc = g_xh + (size_t)xrow * K_IN + xu0 * 8;
    const uint32_t adst = as_b + 2u * (xrow * LDK + xu0 * 8);

    int4     wq[8];
    uint32_t szr[8];

    auto load_chunk = [&](int w, int pbuf) {
        const int g  = w & (NG - 1);
        const int nb = (w >> 6) * BN;
        const int k0 = g * BK;
        #pragma unroll
        for (int j = 0; j < 8; ++j)
            cp16(adst + pbuf * ABYTES + j * 16, xsrc + (size_t)j * 8 + k0);
        asm volatile("cp.async.commit_group;");
        const int* qr = qw + (size_t)(nb + warp) * K_IN + k0 + lane * 4;
        #pragma unroll
        for (int it = 0; it < 8; ++it)
            wq[it] = *reinterpret_cast<const int4*>(qr + (size_t)(it * 4) * K_IN);
        const uint32_t* szp = g_szp + (size_t)g * N_OUT + nb + warp;
        #pragma unroll
        for (int it = 0; it < 8; ++it)
            szr[it] = szp[it * 4];
    };

    load_chunk(w0, 0);

    const __half2 k1032 = __floats2half2_rn(1032.f, 1032.f);
    int seg = 0;

    for (int w = w0; w < w1; ++w) {
        const int p = (w - w0) & 1;
        asm volatile("cp.async.wait_group 0;");

        // ---- dequant + stage w tile into Bs[p] (rows it*4+warp) ----
        __half* Bsb = Bs + p * (BN * LDK);
        #pragma unroll
        for (int it = 0; it < 8; ++it) {
            const int nloc = it * 4 + warp;
            const __half2 szh = *reinterpret_cast<const __half2*>(&szr[it]);
            const __half2 s2 = __half2half2(__low2half(szh));
            const __half2 z2 = __half2half2(__high2half(szh));
            const int4 q = wq[it];
            uint32_t p0 = 0x64006400u | (uint32_t)q.x | ((uint32_t)q.y << 16);
            uint32_t p1 = 0x64006400u | (uint32_t)q.z | ((uint32_t)q.w << 16);
            __half2 h0 = __hsub2(*reinterpret_cast<const __half2*>(&p0), k1032);
            __half2 h1 = __hsub2(*reinterpret_cast<const __half2*>(&p1), k1032);
            __half2 w0h = __hfma2(h0, s2, z2);
            __half2 w1h = __hfma2(h1, s2, z2);
            uint2 pk;
            pk.x = *reinterpret_cast<uint32_t*>(&w0h);
            pk.y = *reinterpret_cast<uint32_t*>(&w1h);
            *reinterpret_cast<uint2*>(&Bsb[nloc * LDK + lane * 4]) = pk;
        }
        __syncthreads();

        // ---- prefetch chunk w+1 (overlaps MMA) ----
        if (w + 1 < w1)
            load_chunk(w + 1, p ^ 1);

        // ---- MMA: 8 k-steps, 4 n-atoms ----
        const uint32_t ab  = a_off  + p * ABYTES;
        const uint32_t bb0 = b_off0 + p * BBYTES;
        const uint32_t bb1 = b_off1 + p * BBYTES;
        #pragma unroll
        for (int kk = 0; kk < 8; ++kk) {
            uint32_t a0, a1, a2, a3;
            ldsm4(a0, a1, a2, a3, ab + kk * 32);
            uint32_t b0, b1, b2, b3, b4, b5, b6, b7;
            ldsm4(b0, b1, b2, b3, bb0 + kk * 32);
            ldsm4(b4, b5, b6, b7, bb1 + kk * 32);
            mma_16816(acc[0], a0, a1, a2, a3, b0, b1);
            mma_16816(acc[1], a0, a1, a2, a3, b2, b3);
            mma_16816(acc[2], a0, a1, a2, a3, b4, b5);
            mma_16816(acc[3], a0, a1, a2, a3, b6, b7);
        }

        // ---- segment boundary: write partial 64x32 block ----
        if (w + 1 == w1 || ((w + 1) >> 6) != (w >> 6)) {
            float* part = g_part + ((size_t)cta * 2 + seg) * (64 * BN);
            const int row = warp * 16 + (lane >> 2);
            #pragma unroll
            for (int j = 0; j < 4; ++j) {
                const int col = j * 8 + (lane & 3) * 2;
                *reinterpret_cast<float2*>(part + row * BN + col) =
                    make_float2(acc[j][0], acc[j][1]);
                *reinterpret_cast<float2*>(part + (row + 8) * BN + col) =
                    make_float2(acc[j][2], acc[j][3]);
                acc[j][0] = acc[j][1] = acc[j][2] = acc[j][3] = 0.f;
            }
            ++seg;
        }
    }
}

extern "C" void kernel_launch(void* const* d_in, const int* in_sizes, int n_in,
                              void* d_out, int out_size) {
    const float* x  = (const float*)d_in[0];   // (64, 8192) fp32
    const int*   qw = (const int*)d_in[1];     // (8192, 8192) int32 in [0,15]
    const float* sz = (const float*)d_in[2];   // (64, 8192, 2) fp32
    float* out = (float*)d_out;                // (64, 8192) fp32

    static bool attr_set = false;
    if (!attr_set) {
        cudaFuncSetAttribute(woq_gemm_kernel,
                             cudaFuncAttributeMaxDynamicSharedMemorySize, SMEM_BYTES);
        attr_set = true;
    }

    const int n_prep = (M_TOK * K_IN / 8) + (NG * N_OUT / 4);  // 196608 threads
    prep_kernel<<<n_prep / 256, 256>>>(x, sz);
    woq_gemm_kernel<<<NCTA, NTHREADS, SMEM_BYTES>>>(qw);
    reduce_kernel<<<(M_TOK * N_OUT / 2) / 256, 256>>>(out);
}